// round 12
// baseline (speedup 1.0000x reference)
#include <cuda_runtime.h>
#include <cooperative_groups.h>
#include <math.h>

namespace cg = cooperative_groups;

#define NB   256
#define NC   768
#define NH   24
#define NHW  576
#define EMBD 2304
#define CS   8               // cluster size (CTAs per (img,b) unit)
#define CHP  (NC / CS)       // 96 channels per CTA
#define KSPLIT 18
#define KB (EMBD / KSPLIT)   // 128
#define SMEM_DYN (CHP * NHW * 4)   // 221184 B: this CTA's channels

// ---- packed f32x2 helpers -------------------------------------------------
__device__ __forceinline__ void fma2(unsigned long long& acc,
                                     unsigned long long a, unsigned long long b) {
    asm("fma.rn.f32x2 %0, %1, %2, %0;" : "+l"(acc) : "l"(a), "l"(b));
}
__device__ __forceinline__ void add2(unsigned long long& acc, unsigned long long a) {
    asm("add.rn.f32x2 %0, %1, %0;" : "+l"(acc) : "l"(a));
}
__device__ __forceinline__ float2 unpack2(unsigned long long v) {
    float2 r;
    asm("mov.b64 {%0, %1}, %2;" : "=f"(r.x), "=f"(r.y) : "l"(v));
    return r;
}

// Scratch (allocation-free rule: __device__ globals)
__device__ float g_emb[2][NB][EMBD];             // unnormalized embeddings
__device__ float g_ssq[2][NB][CS];               // per-rank sum-of-squares
__device__ float g_lpart[KSPLIT][NB][NB];        // GEMM K-split partials
__device__ float g_logitsT[NB][NB];
__device__ float g_lse1[NB];
__device__ float g_diag[NB];
__device__ float g_rowloss[NB];

// ---------------------------------------------------------------------------
// Fused peaks kernel: cluster of 8 CTAs per (img,b); CTA rank r owns channels
// [r*96,(r+1)*96). SINGLE DRAM read: pass A streams own channels into SMEM
// (221KB dynamic) while accumulating the heatmap partial; DSMEM exchanges the
// 8 partials; masks; pass B pools from OWN SMEM. 1 CTA/SM (smem-forced).
// ---------------------------------------------------------------------------
__global__ void __cluster_dims__(CS, 1, 1) __launch_bounds__(NHW)
fused_peaks_kernel(const float* __restrict__ f1, const float* __restrict__ f2) {
    cg::cluster_group cluster = cg::this_cluster();
    const int rank = (int)cluster.block_rank();      // 0..7
    const int unit = blockIdx.x / CS;                // 0..511
    const int b    = unit % NB;
    const int img  = unit / NB;

    // Overlaid static smem region (6912B):
    //   phase 1 (pass-A reduce): buf = float4[2][144]           (4608B)
    //   phase 2 (after sync1)  : s_hm(2304) | s_mmax(2304) | s_mmin(2304)
    __shared__ __align__(16) unsigned char s_un[6912];
    __shared__ __align__(16) float s_hmp[NHW];       // partial heatmap (DSMEM-read)
    __shared__ float s_ssq[18];
    extern __shared__ __align__(16) float4 s_data4[];   // [CHP*144] own channels

    const int t = threadIdx.x;
    const float* __restrict__ fb = (img ? f2 : f1) + (size_t)b * NC * NHW;
    const float4* __restrict__ gbase =
        (const float4*)(fb + (size_t)rank * CHP * NHW);

    // ---- Pass A: stream own 96 channels DRAM -> SMEM, accumulate heatmap.
    // Thread t owns float4-slot s=t%144, channels {t/144 + 4*ci}.
    float4 acc = make_float4(0.f, 0.f, 0.f, 0.f);
    #pragma unroll 8
    for (int ci = 0; ci < 24; ci++) {
        const int idx = ci * 576 + t;
        float4 v = gbase[idx];
        s_data4[idx] = v;
        acc.x += v.x; acc.y += v.y; acc.z += v.z; acc.w += v.w;
    }

    // group-reduce 4 groups -> s_hmp, using 4608B buf (2 phases)
    {
        float4* buf = (float4*)s_un;                 // [2][144]
        const int g = t / 144, s = t % 144;
        if (g >= 2) buf[(g - 2) * 144 + s] = acc;
        __syncthreads();
        if (g < 2) {
            float4 p = buf[g * 144 + s];
            acc.x += p.x; acc.y += p.y; acc.z += p.z; acc.w += p.w;
            buf[g * 144 + s] = acc;
        }
        __syncthreads();
        if (g == 0) {
            float4 p = buf[144 + s];
            ((float4*)s_hmp)[s] = make_float4(acc.x + p.x, acc.y + p.y,
                                              acc.z + p.z, acc.w + p.w);
        }
    }
    cluster.sync();   // s_hmp visible cluster-wide (buf dead from here)

    float* s_hm   = (float*)s_un;                    // [576]
    float* s_mmax = (float*)(s_un + 2304);
    float* s_mmin = (float*)(s_un + 4608);

    // ---- Sum the 8 partial heatmaps via DSMEM
    {
        float v = 0.f;
        #pragma unroll
        for (int r = 0; r < CS; r++) {
            const float* p = (const float*)cluster.map_shared_rank((void*)s_hmp, r);
            v += p[t];
        }
        s_hm[t] = v;
    }
    cluster.sync();   // peers done reading s_hmp; local barrier for s_hm

    // ---- 3x3 border-clipped masks; corners never peaks
    float invmax, invmin;
    {
        const int h = t / NH, w = t % NH;
        const float v = s_hm[t];
        float mx = v, mn = v;
        #pragma unroll
        for (int dh = -1; dh <= 1; dh++) {
            #pragma unroll
            for (int dw = -1; dw <= 1; dw++) {
                int hh = h + dh, ww = w + dw;
                if (hh >= 0 && hh < NH && ww >= 0 && ww < NH) {
                    float nb = s_hm[hh * NH + ww];
                    mx = fmaxf(mx, nb);
                    mn = fminf(mn, nb);
                }
            }
        }
        const bool corner = (h == 0 || h == NH - 1) && (w == 0 || w == NH - 1);
        const bool ismax  = (v >= mx) && !corner;
        const bool ismin  = (v <= mn) && !corner;
        s_mmax[t] = ismax ? 1.f : 0.f;
        s_mmin[t] = ismin ? 1.f : 0.f;
        const int nmax = __syncthreads_count(ismax);
        const int nmin = __syncthreads_count(ismin);
        invmax = 1.f / (float)nmax;
        invmin = 1.f / (float)nmin;
    }
    __syncthreads();   // masks visible to all warps

    // ---- Pass B: masked pooling from OWN SMEM. Warp per channel row.
    {
        const int warp = t >> 5;      // 0..17
        const int lane = t & 31;
        const float invgap = 1.f / (float)NHW;
        float* __restrict__ eb = &g_emb[img][b][0];

        // hoist mask vectors into registers (reused for every channel row)
        const ulonglong2* m2a = (const ulonglong2*)s_mmax;
        const ulonglong2* m2i = (const ulonglong2*)s_mmin;
        ulonglong2 MA[5], MI[5];
        #pragma unroll
        for (int i = 0; i < 4; i++) {
            MA[i] = m2a[lane + (i << 5)];
            MI[i] = m2i[lane + (i << 5)];
        }
        if (lane < 16) { MA[4] = m2a[128 + lane]; MI[4] = m2i[128 + lane]; }

        float ssq = 0.f;
        for (int cc = warp; cc < CHP; cc += 18) {
            const ulonglong2* __restrict__ row2 =
                (const ulonglong2*)(s_data4 + cc * 144);

            unsigned long long am = 0ull, ai = 0ull, ag = 0ull;
            #pragma unroll
            for (int i = 0; i < 4; i++) {
                ulonglong2 x = row2[lane + (i << 5)];
                fma2(am, x.x, MA[i].x); fma2(am, x.y, MA[i].y);
                fma2(ai, x.x, MI[i].x); fma2(ai, x.y, MI[i].y);
                add2(ag, x.x);          add2(ag, x.y);
            }
            if (lane < 16) {
                ulonglong2 x = row2[128 + lane];
                fma2(am, x.x, MA[4].x); fma2(am, x.y, MA[4].y);
                fma2(ai, x.x, MI[4].x); fma2(ai, x.y, MI[4].y);
                add2(ag, x.x);          add2(ag, x.y);
            }
            float2 fm = unpack2(am), fi = unpack2(ai), fg = unpack2(ag);
            float smax = fm.x + fm.y, smin = fi.x + fi.y, sgap = fg.x + fg.y;
            #pragma unroll
            for (int off = 16; off > 0; off >>= 1) {
                smax += __shfl_down_sync(0xffffffffu, smax, off);
                smin += __shfl_down_sync(0xffffffffu, smin, off);
                sgap += __shfl_down_sync(0xffffffffu, sgap, off);
            }
            if (lane == 0) {
                const int c = rank * CHP + cc;
                float a = smax * invmax;
                float m = smin * invmin;
                float g = sgap * invgap;
                eb[c]          = a;
                eb[NC + c]     = m;
                eb[2 * NC + c] = g;
                ssq += a * a + m * m + g * g;
            }
        }
        if (lane == 0) s_ssq[warp] = ssq;
        __syncthreads();
        if (t == 0) {
            float s = 0.f;
            #pragma unroll
            for (int i = 0; i < 18; i++) s += s_ssq[i];
            g_ssq[img][b][rank] = s;
        }
    }
}

// ---------------------------------------------------------------------------
// GEMM on unnormalized embeddings: 64x64 tile, 4x4/thread, K-split 18.
// ---------------------------------------------------------------------------
__global__ __launch_bounds__(256) void gemm_kernel() {
    __shared__ __align__(16) float As[32][68];
    __shared__ __align__(16) float Bs[32][68];
    const int tx = threadIdx.x, ty = threadIdx.y;       // 16x16
    const int tid = ty * 16 + tx;
    const int bi = blockIdx.y * 64, bj = blockIdx.x * 64;
    const int kb0 = blockIdx.z * KB;

    const int lm = tid >> 2;
    const int lk = (tid & 3) * 8;

    float acc[4][4];
    #pragma unroll
    for (int i = 0; i < 4; i++)
        #pragma unroll
        for (int j = 0; j < 4; j++) acc[i][j] = 0.f;

    for (int kc = 0; kc < KB; kc += 32) {
        const int kg = kb0 + kc + lk;
        float4 a0 = *(const float4*)&g_emb[0][bi + lm][kg];
        float4 a1 = *(const float4*)&g_emb[0][bi + lm][kg + 4];
        float4 b0 = *(const float4*)&g_emb[1][bj + lm][kg];
        float4 b1 = *(const float4*)&g_emb[1][bj + lm][kg + 4];
        As[lk + 0][lm] = a0.x; As[lk + 1][lm] = a0.y; As[lk + 2][lm] = a0.z; As[lk + 3][lm] = a0.w;
        As[lk + 4][lm] = a1.x; As[lk + 5][lm] = a1.y; As[lk + 6][lm] = a1.z; As[lk + 7][lm] = a1.w;
        Bs[lk + 0][lm] = b0.x; Bs[lk + 1][lm] = b0.y; Bs[lk + 2][lm] = b0.z; Bs[lk + 3][lm] = b0.w;
        Bs[lk + 4][lm] = b1.x; Bs[lk + 5][lm] = b1.y; Bs[lk + 6][lm] = b1.z; Bs[lk + 7][lm] = b1.w;
        __syncthreads();

        #pragma unroll
        for (int k = 0; k < 32; k++) {
            float4 av = *(const float4*)&As[k][ty * 4];
            float4 bv = *(const float4*)&Bs[k][tx * 4];
            float a[4] = {av.x, av.y, av.z, av.w};
            float bb[4] = {bv.x, bv.y, bv.z, bv.w};
            #pragma unroll
            for (int i = 0; i < 4; i++)
                #pragma unroll
                for (int j = 0; j < 4; j++)
                    acc[i][j] = fmaf(a[i], bb[j], acc[i][j]);
        }
        __syncthreads();
    }

    #pragma unroll
    for (int i = 0; i < 4; i++) {
        float4 v = make_float4(acc[i][0], acc[i][1], acc[i][2], acc[i][3]);
        *(float4*)&g_lpart[blockIdx.z][bi + ty * 4 + i][bj + tx * 4] = v;
    }
}

// ---------------------------------------------------------------------------
// Reduce K-split partials (coalesced), normalize+scale, compute lse1 inline.
// ---------------------------------------------------------------------------
__global__ __launch_bounds__(256) void reduce_kernel(const float* __restrict__ scale_p) {
    const int r = blockIdx.x, t = threadIdx.x;
    const int warp = t >> 5, lane = t & 31;
    __shared__ float sred[8];

    float sq1r = 0.f, sq2t = 0.f;
    #pragma unroll
    for (int c = 0; c < CS; c++) {
        sq1r += g_ssq[0][r][c];
        sq2t += g_ssq[1][t][c];
    }
    const float f = __ldg(scale_p) * rsqrtf(sq1r) * rsqrtf(sq2t);

    float v = 0.f;
    #pragma unroll
    for (int z = 0; z < KSPLIT; z++) v += g_lpart[z][r][t];
    v *= f;
    g_logitsT[t][r] = v;
    if (t == r) g_diag[r] = v;

    float m = v;
    #pragma unroll
    for (int off = 16; off > 0; off >>= 1) m = fmaxf(m, __shfl_xor_sync(0xffffffffu, m, off));
    if (lane == 0) sred[warp] = m;
    __syncthreads();
    float m1 = sred[0];
    #pragma unroll
    for (int i = 1; i < 8; i++) m1 = fmaxf(m1, sred[i]);
    __syncthreads();

    float e1 = expf(v - m1);
    #pragma unroll
    for (int off = 16; off > 0; off >>= 1) e1 += __shfl_xor_sync(0xffffffffu, e1, off);
    if (lane == 0) sred[warp] = e1;
    __syncthreads();
    if (t == 0) {
        float s1 = 0.f;
        #pragma unroll
        for (int i = 0; i < 8; i++) s1 += sred[i];
        g_lse1[r] = m1 + logf(s1);
    }
}

// ---------------------------------------------------------------------------
// lse2 over logitsT rows (coalesced), combine with lse1 and diag.
// ---------------------------------------------------------------------------
__global__ __launch_bounds__(256) void lse2_kernel() {
    const int r = blockIdx.x, t = threadIdx.x;
    const int warp = t >> 5, lane = t & 31;
    __shared__ float sred[8];

    const float x2 = g_logitsT[r][t];

    float n = x2;
    #pragma unroll
    for (int off = 16; off > 0; off >>= 1) n = fmaxf(n, __shfl_xor_sync(0xffffffffu, n, off));
    if (lane == 0) sred[warp] = n;
    __syncthreads();
    float m2 = sred[0];
    #pragma unroll
    for (int i = 1; i < 8; i++) m2 = fmaxf(m2, sred[i]);
    __syncthreads();

    float e2 = expf(x2 - m2);
    #pragma unroll
    for (int off = 16; off > 0; off >>= 1) e2 += __shfl_xor_sync(0xffffffffu, e2, off);
    if (lane == 0) sred[warp] = e2;
    __syncthreads();
    if (t == 0) {
        float s2 = 0.f;
        #pragma unroll
        for (int i = 0; i < 8; i++) s2 += sred[i];
        g_rowloss[r] = g_lse1[r] + (m2 + logf(s2)) - 2.f * g_diag[r];
    }
}

// ---------------------------------------------------------------------------
// Final scalar: mean over rows, /2 (symmetric CE), write to d_out.
// ---------------------------------------------------------------------------
__global__ __launch_bounds__(256) void final_kernel(float* __restrict__ out) {
    float v = g_rowloss[threadIdx.x];
    #pragma unroll
    for (int off = 16; off > 0; off >>= 1)
        v += __shfl_xor_sync(0xffffffffu, v, off);
    __shared__ float sred[8];
    if ((threadIdx.x & 31) == 0) sred[threadIdx.x >> 5] = v;
    __syncthreads();
    if (threadIdx.x == 0) {
        float t = 0.f;
        #pragma unroll
        for (int i = 0; i < 8; i++) t += sred[i];
        out[0] = t * (1.0f / 512.0f);
    }
}

extern "C" void kernel_launch(void* const* d_in, const int* in_sizes, int n_in,
                              void* d_out, int out_size) {
    (void)in_sizes; (void)n_in; (void)out_size;
    const float* f1    = (const float*)d_in[0];
    const float* f2    = (const float*)d_in[1];
    const float* scale = (const float*)d_in[2];

    // Opt into >48KB dynamic smem. Attribute persists; skip during graph
    // capture (set on the earlier correctness call) to keep capture clean.
    cudaStreamCaptureStatus cap = cudaStreamCaptureStatusNone;
    cudaStreamIsCapturing((cudaStream_t)0, &cap);
    if (cap == cudaStreamCaptureStatusNone) {
        cudaFuncSetAttribute(fused_peaks_kernel,
                             cudaFuncAttributeMaxDynamicSharedMemorySize, SMEM_DYN);
    }

    fused_peaks_kernel<<<NB * 2 * CS, NHW, SMEM_DYN>>>(f1, f2);
    gemm_kernel  <<<dim3(4, 4, KSPLIT), dim3(16, 16)>>>();
    reduce_kernel<<<NB, 256>>>(scale);
    lse2_kernel  <<<NB, 256>>>();
    final_kernel <<<1, 256>>>((float*)d_out);
}

// round 13
// speedup vs baseline: 1.7352x; 1.7352x over previous
#include <cuda_runtime.h>
#include <math.h>

#define NB   256
#define NC   768
#define NH   24
#define NHW  576
#define EMBD 2304
#define HM_Z  4          // z-chunks for heatmap (192 ch each)
#define PL_CHUNKS 6      // channel chunks for masked pooling (128 ch each)
#define KSPLIT 12
#define KB (EMBD / KSPLIT)   // 192

// ---- packed f32x2 helpers -------------------------------------------------
__device__ __forceinline__ void fma2(unsigned long long& acc,
                                     unsigned long long a, unsigned long long b) {
    asm("fma.rn.f32x2 %0, %1, %2, %0;" : "+l"(acc) : "l"(a), "l"(b));
}
__device__ __forceinline__ void add2(unsigned long long& acc, unsigned long long a) {
    asm("add.rn.f32x2 %0, %1, %0;" : "+l"(acc) : "l"(a));
}
__device__ __forceinline__ float2 unpack2(unsigned long long v) {
    float2 r;
    asm("mov.b64 {%0, %1}, %2;" : "=f"(r.x), "=f"(r.y) : "l"(v));
    return r;
}

// Scratch (allocation-free rule: __device__ globals)
__device__ float g_hmp[2][NB][HM_Z][NHW];        // partial heatmaps (4.7MB)
__device__ float g_mask[2][NB][2][NHW];          // [0]=max mask, [1]=min mask
__device__ float g_inv[2][NB][2];                // 1/nmax, 1/nmin
__device__ float g_emb[2][NB][EMBD];
__device__ float g_lpart[KSPLIT][NB][NB];        // GEMM K-split partials (3MB)
__device__ float g_logits[NB][NB];
__device__ float g_logitsT[NB][NB];
__device__ float g_rowloss[NB];

// ---------------------------------------------------------------------------
// K1: partial heatmaps. grid (NB, 2, HM_Z), block 576.
// Thread = (group g = t/144, slot s = t%144); owns 4 pixels (float4 slot s),
// sums 48 channels. Groups block-reduced in smem -> ONE partial per block.
// ---------------------------------------------------------------------------
__global__ __launch_bounds__(NHW) void hm_kernel(const float* __restrict__ f1,
                                                 const float* __restrict__ f2) {
    const int img = blockIdx.y;
    const int b   = blockIdx.x;
    const int z   = blockIdx.z;
    const int g   = threadIdx.x / 144;
    const int s   = threadIdx.x % 144;

    __shared__ __align__(16) float4 s_part[4][144];

    const float* fb = (img ? f2 : f1) + (size_t)b * NC * NHW
                    + (size_t)(z * 192 + g * 48) * NHW;
    const float4* __restrict__ base = (const float4*)fb + s;

    float ax = 0.f, ay = 0.f, az = 0.f, aw = 0.f;
    #pragma unroll 8
    for (int ci = 0; ci < 48; ci++) {
        float4 v = base[(size_t)ci * 144];       // 144 float4 per channel row
        ax += v.x; ay += v.y; az += v.z; aw += v.w;
    }
    s_part[g][s] = make_float4(ax, ay, az, aw);
    __syncthreads();

    if (g == 0) {                                 // 144 threads finalize
        float4 p0 = s_part[0][s], p1 = s_part[1][s];
        float4 p2 = s_part[2][s], p3 = s_part[3][s];
        float4 o = make_float4((p0.x + p1.x) + (p2.x + p3.x),
                               (p0.y + p1.y) + (p2.y + p3.y),
                               (p0.z + p1.z) + (p2.z + p3.z),
                               (p0.w + p1.w) + (p2.w + p3.w));
        ((float4*)&g_hmp[img][b][z][0])[s] = o;
    }
}

// ---------------------------------------------------------------------------
// K2: masks from heatmap. grid (NB, 2), block 576. Tiny.
// ---------------------------------------------------------------------------
__global__ __launch_bounds__(NHW) void mask_kernel() {
    const int img = blockIdx.y, b = blockIdx.x, hw = threadIdx.x;
    __shared__ float s_hm[NHW];

    float v = 0.f;
    #pragma unroll
    for (int p = 0; p < HM_Z; p++) v += g_hmp[img][b][p][hw];
    s_hm[hw] = v;
    __syncthreads();

    const int h = hw / NH, w = hw % NH;
    float mx = v, mn = v;
    #pragma unroll
    for (int dh = -1; dh <= 1; dh++) {
        #pragma unroll
        for (int dw = -1; dw <= 1; dw++) {
            int hh = h + dh, ww = w + dw;
            if (hh >= 0 && hh < NH && ww >= 0 && ww < NH) {
                float nb = s_hm[hh * NH + ww];
                mx = fmaxf(mx, nb);
                mn = fminf(mn, nb);
            }
        }
    }
    const bool corner = (h == 0 || h == NH - 1) && (w == 0 || w == NH - 1);
    const bool ismax  = (v >= mx) && !corner;
    const bool ismin  = (v <= mn) && !corner;
    g_mask[img][b][0][hw] = ismax ? 1.f : 0.f;
    g_mask[img][b][1][hw] = ismin ? 1.f : 0.f;
    const int nmax = __syncthreads_count(ismax);
    const int nmin = __syncthreads_count(ismin);
    if (hw == 0) {
        g_inv[img][b][0] = 1.f / (float)nmax;
        g_inv[img][b][1] = 1.f / (float)nmin;
    }
}

// ---------------------------------------------------------------------------
// K3: masked pooling with packed f32x2 FMAs. grid (NB, 2, PL_CHUNKS), 256 thr.
// ---------------------------------------------------------------------------
__global__ __launch_bounds__(256) void pool_kernel(const float* __restrict__ f1,
                                                   const float* __restrict__ f2) {
    const int img = blockIdx.y;
    const int b   = blockIdx.x;
    const int ch0 = blockIdx.z * (NC / PL_CHUNKS);
    const float* __restrict__ fb = (img ? f2 : f1) + (size_t)b * NC * NHW;

    __shared__ __align__(16) float s_mmax[NHW];
    __shared__ __align__(16) float s_mmin[NHW];
    __shared__ float s_inv[2];

    for (int i = threadIdx.x; i < NHW; i += 256) {
        s_mmax[i] = g_mask[img][b][0][i];
        s_mmin[i] = g_mask[img][b][1][i];
    }
    if (threadIdx.x < 2) s_inv[threadIdx.x] = g_inv[img][b][threadIdx.x];
    __syncthreads();

    const int warp = threadIdx.x >> 5;
    const int lane = threadIdx.x & 31;
    const float invmax = s_inv[0];
    const float invmin = s_inv[1];
    const float invgap = 1.f / (float)NHW;
    const ulonglong2* __restrict__ m2a = (const ulonglong2*)s_mmax;
    const ulonglong2* __restrict__ m2i = (const ulonglong2*)s_mmin;
    float* __restrict__ eb = &g_emb[img][b][0];

    #pragma unroll 2
    for (int ci = 0; ci < 16; ci++) {
        const int c = ch0 + warp + (ci << 3);
        const ulonglong2* __restrict__ row2 = (const ulonglong2*)(fb + (size_t)c * NHW);

        unsigned long long am = 0ull, ai = 0ull, ag = 0ull;
        #pragma unroll
        for (int i = 0; i < 4; i++) {                // 4*32 = 128 of 144 float4
            int idx = lane + (i << 5);
            ulonglong2 x  = row2[idx];
            ulonglong2 ma = m2a[idx];
            ulonglong2 mi = m2i[idx];
            fma2(am, x.x, ma.x); fma2(am, x.y, ma.y);
            fma2(ai, x.x, mi.x); fma2(ai, x.y, mi.y);
            add2(ag, x.x);       add2(ag, x.y);
        }
        if (lane < 16) {                             // remaining 16 float4
            int idx = 128 + lane;
            ulonglong2 x  = row2[idx];
            ulonglong2 ma = m2a[idx];
            ulonglong2 mi = m2i[idx];
            fma2(am, x.x, ma.x); fma2(am, x.y, ma.y);
            fma2(ai, x.x, mi.x); fma2(ai, x.y, mi.y);
            add2(ag, x.x);       add2(ag, x.y);
        }
        float2 fm = unpack2(am), fi = unpack2(ai), fg = unpack2(ag);
        float smax = fm.x + fm.y, smin = fi.x + fi.y, sgap = fg.x + fg.y;
        #pragma unroll
        for (int off = 16; off > 0; off >>= 1) {
            smax += __shfl_down_sync(0xffffffffu, smax, off);
            smin += __shfl_down_sync(0xffffffffu, smin, off);
            sgap += __shfl_down_sync(0xffffffffu, sgap, off);
        }
        if (lane == 0) {
            eb[c]          = smax * invmax;
            eb[NC + c]     = smin * invmin;
            eb[2 * NC + c] = sgap * invgap;
        }
    }
}

// ---------------------------------------------------------------------------
// L2-normalize each 2304-d embedding in place. One block per (img, b).
// ---------------------------------------------------------------------------
__global__ __launch_bounds__(256) void norm_kernel() {
    const int img = blockIdx.y, b = blockIdx.x;
    float* __restrict__ e = &g_emb[img][b][0];

    float vals[9];
    float ss = 0.f;
    #pragma unroll
    for (int q = 0; q < 9; q++) {
        float x = e[threadIdx.x + q * 256];
        vals[q] = x;
        ss += x * x;
    }
    #pragma unroll
    for (int off = 16; off > 0; off >>= 1)
        ss += __shfl_xor_sync(0xffffffffu, ss, off);

    __shared__ float sred[8];
    __shared__ float s_inv;
    if ((threadIdx.x & 31) == 0) sred[threadIdx.x >> 5] = ss;
    __syncthreads();
    if (threadIdx.x == 0) {
        float t = 0.f;
        #pragma unroll
        for (int i = 0; i < 8; i++) t += sred[i];
        s_inv = 1.f / sqrtf(t);
    }
    __syncthreads();
    const float inv = s_inv;
    #pragma unroll
    for (int q = 0; q < 9; q++) e[threadIdx.x + q * 256] = vals[q] * inv;
}

// ---------------------------------------------------------------------------
// GEMM: 64x64 tile, 16x16 threads, 4x4 per thread, K-split 12 (192 CTAs).
// Transposed smem tiles ([k][m]) so inner loop does 2x LDS.128 per 16 FMA.
// ---------------------------------------------------------------------------
__global__ __launch_bounds__(256) void gemm_kernel() {
    __shared__ __align__(16) float As[32][68];   // [k][m], pad 4 keeps 16B align
    __shared__ __align__(16) float Bs[32][68];
    const int tx = threadIdx.x, ty = threadIdx.y;       // 16x16
    const int tid = ty * 16 + tx;
    const int bi = blockIdx.y * 64, bj = blockIdx.x * 64;
    const int kb0 = blockIdx.z * KB;

    const int lm = tid >> 2;          // 0..63 : m row to load
    const int lk = (tid & 3) * 8;     // 0,8,16,24 : k start (8 floats)

    float acc[4][4];
    #pragma unroll
    for (int i = 0; i < 4; i++)
        #pragma unroll
        for (int j = 0; j < 4; j++) acc[i][j] = 0.f;

    for (int kc = 0; kc < KB; kc += 32) {
        const int kg = kb0 + kc + lk;
        float4 a0 = *(const float4*)&g_emb[0][bi + lm][kg];
        float4 a1 = *(const float4*)&g_emb[0][bi + lm][kg + 4];
        float4 b0 = *(const float4*)&g_emb[1][bj + lm][kg];
        float4 b1 = *(const float4*)&g_emb[1][bj + lm][kg + 4];
        As[lk + 0][lm] = a0.x; As[lk + 1][lm] = a0.y; As[lk + 2][lm] = a0.z; As[lk + 3][lm] = a0.w;
        As[lk + 4][lm] = a1.x; As[lk + 5][lm] = a1.y; As[lk + 6][lm] = a1.z; As[lk + 7][lm] = a1.w;
        Bs[lk + 0][lm] = b0.x; Bs[lk + 1][lm] = b0.y; Bs[lk + 2][lm] = b0.z; Bs[lk + 3][lm] = b0.w;
        Bs[lk + 4][lm] = b1.x; Bs[lk + 5][lm] = b1.y; Bs[lk + 6][lm] = b1.z; Bs[lk + 7][lm] = b1.w;
        __syncthreads();

        #pragma unroll
        for (int k = 0; k < 32; k++) {
            float4 av = *(const float4*)&As[k][ty * 4];
            float4 bv = *(const float4*)&Bs[k][tx * 4];
            float a[4] = {av.x, av.y, av.z, av.w};
            float bb[4] = {bv.x, bv.y, bv.z, bv.w};
            #pragma unroll
            for (int i = 0; i < 4; i++)
                #pragma unroll
                for (int j = 0; j < 4; j++)
                    acc[i][j] = fmaf(a[i], bb[j], acc[i][j]);
        }
        __syncthreads();
    }

    #pragma unroll
    for (int i = 0; i < 4; i++) {
        float4 v = make_float4(acc[i][0], acc[i][1], acc[i][2], acc[i][3]);
        *(float4*)&g_lpart[blockIdx.z][bi + ty * 4 + i][bj + tx * 4] = v;
    }
}

// ---------------------------------------------------------------------------
// Reduce K-split partials, apply scale, emit logits and logitsT.
// grid (NB), block 256: thread t handles column t of row blockIdx.x.
// ---------------------------------------------------------------------------
__global__ __launch_bounds__(256) void reduce_kernel(const float* __restrict__ scale_p) {
    const int r = blockIdx.x, t = threadIdx.x;
    float v = 0.f;
    #pragma unroll
    for (int z = 0; z < KSPLIT; z++) v += g_lpart[z][r][t];
    v *= __ldg(scale_p);
    g_logits[r][t]  = v;
    g_logitsT[t][r] = v;
}

// ---------------------------------------------------------------------------
// Per-row: lse(row of logits) + lse(row of logitsT) - 2*diag
// ---------------------------------------------------------------------------
__global__ __launch_bounds__(256) void lse_kernel() {
    const int r = blockIdx.x, t = threadIdx.x;
    const int warp = t >> 5, lane = t & 31;
    __shared__ float sred[8];

    const float x1 = g_logits[r][t];
    const float x2 = g_logitsT[r][t];

    float m = x1;
    #pragma unroll
    for (int off = 16; off > 0; off >>= 1) m = fmaxf(m, __shfl_xor_sync(0xffffffffu, m, off));
    if (lane == 0) sred[warp] = m;
    __syncthreads();
    float m1 = sred[0];
    #pragma unroll
    for (int i = 1; i < 8; i++) m1 = fmaxf(m1, sred[i]);
    __syncthreads();

    float e1 = expf(x1 - m1);
    #pragma unroll
    for (int off = 16; off > 0; off >>= 1) e1 += __shfl_xor_sync(0xffffffffu, e1, off);
    if (lane == 0) sred[warp] = e1;
    __syncthreads();
    float s1 = 0.f;
    #pragma unroll
    for (int i = 0; i < 8; i++) s1 += sred[i];
    __syncthreads();

    float n = x2;
    #pragma unroll
    for (int off = 16; off > 0; off >>= 1) n = fmaxf(n, __shfl_xor_sync(0xffffffffu, n, off));
    if (lane == 0) sred[warp] = n;
    __syncthreads();
    float m2 = sred[0];
    #pragma unroll
    for (int i = 1; i < 8; i++) m2 = fmaxf(m2, sred[i]);
    __syncthreads();

    float e2 = expf(x2 - m2);
    #pragma unroll
    for (int off = 16; off > 0; off >>= 1) e2 += __shfl_xor_sync(0xffffffffu, e2, off);
    if (lane == 0) sred[warp] = e2;
    __syncthreads();
    float s2 = 0.f;
    #pragma unroll
    for (int i = 0; i < 8; i++) s2 += sred[i];

    if (t == 0) {
        float lse1 = m1 + logf(s1);
        float lse2 = m2 + logf(s2);
        g_rowloss[r] = lse1 + lse2 - 2.f * g_logits[r][r];
    }
}

// ---------------------------------------------------------------------------
// Final scalar: mean over rows, /2 (symmetric CE), write to d_out.
// ---------------------------------------------------------------------------
__global__ __launch_bounds__(256) void final_kernel(float* __restrict__ out) {
    float v = g_rowloss[threadIdx.x];
    #pragma unroll
    for (int off = 16; off > 0; off >>= 1)
        v += __shfl_xor_sync(0xffffffffu, v, off);
    __shared__ float sred[8];
    if ((threadIdx.x & 31) == 0) sred[threadIdx.x >> 5] = v;
    __syncthreads();
    if (threadIdx.x == 0) {
        float t = 0.f;
        #pragma unroll
        for (int i = 0; i < 8; i++) t += sred[i];
        out[0] = t * (1.0f / 512.0f);
    }
}

extern "C" void kernel_launch(void* const* d_in, const int* in_sizes, int n_in,
                              void* d_out, int out_size) {
    (void)in_sizes; (void)n_in; (void)out_size;
    const float* f1    = (const float*)d_in[0];
    const float* f2    = (const float*)d_in[1];
    const float* scale = (const float*)d_in[2];

    hm_kernel    <<<dim3(NB, 2, HM_Z),      NHW>>>(f1, f2);
    mask_kernel  <<<dim3(NB, 2),            NHW>>>();
    pool_kernel  <<<dim3(NB, 2, PL_CHUNKS), 256>>>(f1, f2);
    norm_kernel  <<<dim3(NB, 2),            256>>>();
    gemm_kernel  <<<dim3(4, 4, KSPLIT), dim3(16, 16)>>>();
    reduce_kernel<<<NB, 256>>>(scale);
    lse_kernel   <<<NB, 256>>>();
    final_kernel <<<1, 256>>>((float*)d_out);
}